// round 11
// baseline (speedup 1.0000x reference)
#include <cuda_runtime.h>
#include <math.h>

// GraphQNN: h = tanh(W @ x); exp_val computed analytically (Heisenberg picture).
//
//   layer-1 CNOT chain: Z_0 invariant; layer-1 RX(t') on q0: Z -> cos t' Z + sin t' Y
//   layer-0 CNOT chain: Z_0 -> Z_0 ; Y_0 -> Y_0 X_1
//   product state per qubit q: RZ(p_q) RX(t_q) RY(2 h_q)|0>
//     <Z>_0 = cos t0 cos 2h0
//     <Y>_0 = sin p0 sin 2h0 - cos p0 sin t0 cos 2h0
//     <X>_1 = cos p1 sin 2h1 + sin p1 sin t1 cos 2h1
//   exp_val = cos t' <Z>_0 + sin t' <Y>_0 <X>_1     (t' = q_params[46])
//
// FINAL: R10 structure (1x768, zero barriers/smem; tail warp self-contained
// with hoisted qp loads + parallel lane0/lane16 h-trig) + MUFU-path tanh
// (tanh s = 1 - 2/(e^{2s}+1) via __expf) replacing branchy precise tanhf on
// the critical h-warp chains. ~1e-6 h error, 500x under the 1e-3 gate.

#define NQ 23
#define IN_DIM 1024

__device__ __forceinline__ float fast_tanhf(float s) {
    // exact at saturation: e^{2s}->inf => 1, ->0 => -1
    return 1.0f - 2.0f / (__expf(2.0f * s) + 1.0f);
}

__global__ void __launch_bounds__((NQ + 1) * 32)
graphqnn_kernel(const float* __restrict__ x,
                const float* __restrict__ W,
                const float* __restrict__ qp,
                float* __restrict__ out) {
    const int warp = threadIdx.x >> 5;
    const int lane = threadIdx.x & 31;

    const float4* xr = reinterpret_cast<const float4*>(x);

    if (warp < NQ) {
        // ---- h-row warp: 1024-dot, 8 float4 per lane, 4 accumulators ----
        const float4* wr = reinterpret_cast<const float4*>(W + warp * IN_DIM);
        float4 a[8], b[8];
        #pragma unroll
        for (int i = 0; i < 8; ++i) { a[i] = wr[lane + 32 * i]; b[i] = xr[lane + 32 * i]; }

        float s0 = 0.f, s1 = 0.f, s2 = 0.f, s3 = 0.f;
        #pragma unroll
        for (int i = 0; i < 8; i += 4) {
            s0 += a[i+0].x*b[i+0].x + a[i+0].y*b[i+0].y + a[i+0].z*b[i+0].z + a[i+0].w*b[i+0].w;
            s1 += a[i+1].x*b[i+1].x + a[i+1].y*b[i+1].y + a[i+1].z*b[i+1].z + a[i+1].w*b[i+1].w;
            s2 += a[i+2].x*b[i+2].x + a[i+2].y*b[i+2].y + a[i+2].z*b[i+2].z + a[i+2].w*b[i+2].w;
            s3 += a[i+3].x*b[i+3].x + a[i+3].y*b[i+3].y + a[i+3].z*b[i+3].z + a[i+3].w*b[i+3].w;
        }
        float s = (s0 + s1) + (s2 + s3);
        #pragma unroll
        for (int o = 16; o > 0; o >>= 1)
            s += __shfl_xor_sync(0xffffffffu, s, o);
        if (lane == 0) out[warp] = fast_tanhf(s);
    } else {
        // ---- tail warp: lanes 0-15 -> row 0 dot, lanes 16-31 -> row 1 dot ----
        // qp loads first: in flight alongside the W/x streams (broadcast LDG)
        float q_t0 = qp[0];          // t0: layer 0, qubit 0, RX
        float q_p0 = qp[1];          // p0: layer 0, qubit 0, RZ
        float q_t1 = qp[2];          // t1: layer 0, qubit 1, RX
        float q_p1 = qp[3];          // p1: layer 0, qubit 1, RZ
        float q_tp = qp[2 * NQ];     // t' = q_params[46]

        const int half = lane >> 4;          // 0 or 1 = row
        const int hl   = lane & 15;          // lane within half
        const float4* wr = reinterpret_cast<const float4*>(W + half * IN_DIM);

        float s0 = 0.f, s1 = 0.f, s2 = 0.f, s3 = 0.f;
        #pragma unroll
        for (int i = 0; i < 16; i += 4) {
            float4 a0 = wr[hl + 16*(i+0)], b0 = xr[hl + 16*(i+0)];
            float4 a1 = wr[hl + 16*(i+1)], b1 = xr[hl + 16*(i+1)];
            float4 a2 = wr[hl + 16*(i+2)], b2 = xr[hl + 16*(i+2)];
            float4 a3 = wr[hl + 16*(i+3)], b3 = xr[hl + 16*(i+3)];
            s0 += a0.x*b0.x + a0.y*b0.y + a0.z*b0.z + a0.w*b0.w;
            s1 += a1.x*b1.x + a1.y*b1.y + a1.z*b1.z + a1.w*b1.w;
            s2 += a2.x*b2.x + a2.y*b2.y + a2.z*b2.z + a2.w*b2.w;
            s3 += a3.x*b3.x + a3.y*b3.y + a3.z*b3.z + a3.w*b3.w;
        }

        // qp trig (all lanes, redundant) -- overlaps the load/FFMA stream
        float ct0, st0, cp0, sp0, st1, cp1, sp1, ctp, stp;
        __sincosf(q_t0, &st0, &ct0);
        __sincosf(q_p0, &sp0, &cp0);
        st1 = __sinf(q_t1);
        __sincosf(q_p1, &sp1, &cp1);
        __sincosf(q_tp, &stp, &ctp);

        float s = (s0 + s1) + (s2 + s3);
        // reduce within each 16-lane half
        #pragma unroll
        for (int o = 8; o > 0; o >>= 1)
            s += __shfl_xor_sync(0xffffffffu, s, o);

        // lane 0 and lane 16 compute their row's tanh + sincos in parallel
        float h = fast_tanhf(s);                 // lane0: h0, lane16: h1
        float s2h, c2h;
        __sincosf(2.0f * h, &s2h, &c2h);

        float s2h1 = __shfl_sync(0xffffffffu, s2h, 16);
        float c2h1 = __shfl_sync(0xffffffffu, c2h, 16);

        if (lane == 0) {
            float z0 = ct0 * c2h;
            float y0 = sp0 * s2h - cp0 * st0 * c2h;
            float x1 = cp1 * s2h1 + sp1 * st1 * c2h1;
            out[NQ] = ctp * z0 + stp * y0 * x1;
        }
    }
}

extern "C" void kernel_launch(void* const* d_in, const int* in_sizes, int n_in,
                              void* d_out, int out_size) {
    const float* x  = (const float*)d_in[0];
    const float* W  = (const float*)d_in[1];
    const float* qp = (const float*)d_in[2];
    float* out = (float*)d_out;
    graphqnn_kernel<<<1, (NQ + 1) * 32>>>(x, W, qp, out);
}